// round 14
// baseline (speedup 1.0000x reference)
#include <cuda_runtime.h>
#include <cuda_bf16.h>
#include <cstdint>

// ---------------- constants ----------------
#define BATCH 4
#define T_TOTAL 35968706LL          // sum of all hypernet parameter counts
#define T2 (T_TOTAL / 2)            // 17,984,353 float2 columns (T_TOTAL is even)

// ---------------- device scratch (no allocation allowed) ----------------
__device__ float g_bufA[4 * 4 * 112 * 112];   // 200,704 floats (largest intermediate)
__device__ float g_bufB[4 * 8 * 56 * 56];     // 100,352 floats
__device__ float g_q[BATCH * 16];             // quantized latents for the big GEMM

// ---------------- templated 4x4 stride-2 pad-1 conv (full unroll) ----------------
// R7-proven configuration. SPLIT > 1: Cin reduction split across SPLIT adjacent
// lanes, reduced with __shfl_xor_sync.
template<int CIN, int COUT, int HIN, int HOUT, bool ACT, int SPLIT, int TPB>
__global__ void __launch_bounds__(TPB) convT(const float* __restrict__ in,
                                             const float* __restrict__ w,
                                             const float* __restrict__ bias,
                                             float* __restrict__ out) {
    constexpr int CPS = CIN / SPLIT;
    int tid = blockIdx.x * TPB + threadIdx.x;
    constexpr int TOTAL = BATCH * COUT * HOUT * HOUT * SPLIT;
    if (tid >= TOTAL) return;   // grids are exact multiples; never splits a warp

    int s = tid % SPLIT;
    int o = tid / SPLIT;
    int ow = o % HOUT;
    int oh = (o / HOUT) % HOUT;
    int co = (o / (HOUT * HOUT)) % COUT;
    int b  = o / (HOUT * HOUT * COUT);

    float acc = 0.0f;
    int ih0 = oh * 2 - 1;
    int iw0 = ow * 2 - 1;

    const float* wbase = w + ((size_t)co * CIN + s * CPS) * 16;
    const float* ibase = in + ((size_t)b * CIN + s * CPS) * HIN * HIN;

    #pragma unroll
    for (int ci = 0; ci < CPS; ci++) {
        const float* ip = ibase + (size_t)ci * HIN * HIN;
        const float* wp = wbase + ci * 16;
        #pragma unroll
        for (int kh = 0; kh < 4; kh++) {
            int ih = ih0 + kh;
            bool rowok = (unsigned)ih < (unsigned)HIN;
            #pragma unroll
            for (int kw = 0; kw < 4; kw++) {
                int iw = iw0 + kw;
                bool ok = rowok && ((unsigned)iw < (unsigned)HIN);
                float v = ok ? __ldg(ip + (size_t)ih * HIN + iw) : 0.0f;
                acc = fmaf(v, __ldg(wp + kh * 4 + kw), acc);
            }
        }
    }

    // in-warp reduction across the SPLIT slices (adjacent lanes)
    #pragma unroll
    for (int off = SPLIT / 2; off > 0; off >>= 1)
        acc += __shfl_xor_sync(0xffffffffu, acc, off);

    if (s == 0) {
        acc += bias[co];
        if (ACT) acc = (acc >= 0.0f) ? acc : 0.01f * acc;
        out[o] = acc;
    }
}

// ---------------- head: avgpool + fc1 + fc2 + VQ + loss ----------------
// conv5 output (bias already applied, no activation): [b][c][49]
__global__ void head_k(const float* __restrict__ conv5,
                       const float* __restrict__ fc1_w, const float* __restrict__ fc1_b,
                       const float* __restrict__ fc2_w, const float* __restrict__ fc2_b,
                       const float* __restrict__ emb,
                       float* __restrict__ loss_out) {
    __shared__ float pooled[BATCH * 64];
    __shared__ float h[BATCH * 16];
    __shared__ float e[BATCH * 16];
    __shared__ float qv[BATCH * 16];
    int tid = threadIdx.x;   // 256 threads

    {
        int b = tid / 64, c = tid % 64;
        const float* p = conv5 + (size_t)(b * 64 + c) * 49;
        float sum = 0.0f;
        #pragma unroll
        for (int i = 0; i < 49; i++) sum += p[i];
        pooled[b * 64 + c] = sum * (1.0f / 49.0f);
    }
    __syncthreads();

    if (tid < 64) {
        int b = tid / 16, i = tid % 16;
        float s = fc1_b[i];
        #pragma unroll
        for (int c = 0; c < 64; c++) s += pooled[b * 64 + c] * fc1_w[i * 64 + c];
        h[b * 16 + i] = (s >= 0.0f) ? s : 0.01f * s;
    }
    __syncthreads();

    if (tid < 64) {
        int b = tid / 16, j = tid % 16;
        float s = fc2_b[j];
        #pragma unroll
        for (int i = 0; i < 16; i++) s += h[b * 16 + i] * fc2_w[j * 16 + i];
        e[b * 16 + j] = s;
    }
    __syncthreads();

    if (tid < BATCH) {
        int b = tid;
        float best = 3.402823e38f;
        int bi = 0;
        for (int j = 0; j < 4; j++) {
            float d = 0.0f;
            #pragma unroll
            for (int k = 0; k < 16; k++) {
                float diff = e[b * 16 + k] - emb[j * 16 + k];
                d += diff * diff;
            }
            if (d < best) { best = d; bi = j; }
        }
        #pragma unroll
        for (int k = 0; k < 16; k++) qv[b * 16 + k] = emb[bi * 16 + k];
    }
    __syncthreads();

    if (tid == 0) {
        float s = 0.0f;
        #pragma unroll
        for (int n = 0; n < 64; n++) {
            float d = qv[n] - e[n];
            s += d * d;
        }
        *loss_out = 1.25f * (s * (1.0f / 64.0f));   // q_lat + 0.25 * e_lat
        #pragma unroll
        for (int n = 0; n < 64; n++) g_q[n] = qv[n];
    }
}

// ---------------- big GEMM: flat = q @ W_all, [4,16] x [16, T_TOTAL] ----------------
// Pure HBM streaming: read 2.30 GB of W, write 0.575 GB of output.
// CHANGE vs R9 (which measured 396.9 us @ DRAM=90.7%, occ=44.1%, regs=64):
// k-loop split into two halves of 8 -> only 8 float2 resident at once.
// Regs ~40 -> 6 blocks/SM = 48 warps (75% occ) for better DRAM latency tolerance.
__global__ void __launch_bounds__(256) hyper_gemm_k(const float* __restrict__ W,
                                                    float* __restrict__ out) {
    __shared__ float qs[64];
    if (threadIdx.x < 64) qs[threadIdx.x] = g_q[threadIdx.x];
    __syncthreads();

    long long t2 = (long long)blockIdx.x * blockDim.x + threadIdx.x;
    if (t2 >= T2) return;

    float ax0 = 0.f, ay0 = 0.f, ax1 = 0.f, ay1 = 0.f;
    float ax2 = 0.f, ay2 = 0.f, ax3 = 0.f, ay3 = 0.f;

    #pragma unroll
    for (int half = 0; half < 2; half++) {
        float2 w[8];
        #pragma unroll
        for (int k = 0; k < 8; k++) {
            w[k] = __ldcs((const float2*)(W + (size_t)(half * 8 + k) * T_TOTAL) + t2);
        }
        #pragma unroll
        for (int k = 0; k < 8; k++) {
            int kk = half * 8 + k;
            float q0 = qs[0 * 16 + kk];
            float q1 = qs[1 * 16 + kk];
            float q2 = qs[2 * 16 + kk];
            float q3 = qs[3 * 16 + kk];
            ax0 = fmaf(q0, w[k].x, ax0);  ay0 = fmaf(q0, w[k].y, ay0);
            ax1 = fmaf(q1, w[k].x, ax1);  ay1 = fmaf(q1, w[k].y, ay1);
            ax2 = fmaf(q2, w[k].x, ax2);  ay2 = fmaf(q2, w[k].y, ay2);
            ax3 = fmaf(q3, w[k].x, ax3);  ay3 = fmaf(q3, w[k].y, ay3);
        }
    }

    __stcs((float2*)(out + 0 * T_TOTAL) + t2, make_float2(ax0, ay0));
    __stcs((float2*)(out + 1 * T_TOTAL) + t2, make_float2(ax1, ay1));
    __stcs((float2*)(out + 2 * T_TOTAL) + t2, make_float2(ax2, ay2));
    __stcs((float2*)(out + 3 * T_TOTAL) + t2, make_float2(ax3, ay3));
}

// ---------------- launch ----------------
extern "C" void kernel_launch(void* const* d_in, const int* in_sizes, int n_in,
                              void* d_out, int out_size) {
    const float* rgb   = (const float*)d_in[0];
    const float* cw1   = (const float*)d_in[1];
    const float* cb1   = (const float*)d_in[2];
    const float* cw2   = (const float*)d_in[3];
    const float* cb2   = (const float*)d_in[4];
    const float* cw3   = (const float*)d_in[5];
    const float* cb3   = (const float*)d_in[6];
    const float* cw4   = (const float*)d_in[7];
    const float* cb4   = (const float*)d_in[8];
    const float* cw5   = (const float*)d_in[9];
    const float* cb5   = (const float*)d_in[10];
    const float* fc1_w = (const float*)d_in[11];
    const float* fc1_b = (const float*)d_in[12];
    const float* fc2_w = (const float*)d_in[13];
    const float* fc2_b = (const float*)d_in[14];
    const float* emb   = (const float*)d_in[15];
    const float* W_all = (const float*)d_in[16];

    float* out = (float*)d_out;
    float* loss_ptr = out + (size_t)out_size - 1;   // flat first, loss scalar last

    float* bufA;  cudaGetSymbolAddress((void**)&bufA, g_bufA);
    float* bufB;  cudaGetSymbolAddress((void**)&bufB, g_bufB);

    // ---- exact R7 encoder configuration (best measured: 453.4 us total) ----
    // conv1: 3->4,  224->112, act — 200,704 threads
    convT<3, 4, 224, 112, true, 1, 256><<<784, 256>>>(rgb, cw1, cb1, bufA);
    // conv2: 4->8,  112->56, act — 100,352 threads
    convT<4, 8, 112, 56, true, 1, 256><<<392, 256>>>(bufA, cw2, cb2, bufB);
    // conv3: 8->16, 56->28, act, SPLIT=4 (shuffle) — 200,704 threads
    convT<8, 16, 56, 28, true, 4, 256><<<784, 256>>>(bufB, cw3, cb3, bufA);
    // conv4: 16->32, 28->14, act, SPLIT=4 (shuffle) — 100,352 threads
    convT<16, 32, 28, 14, true, 4, 128><<<784, 128>>>(bufA, cw4, cb4, bufB);
    // conv5: 32->64, 14->7, NO act, SPLIT=8 (shuffle), bias applied — 100,352 threads
    convT<32, 64, 14, 7, false, 8, 128><<<784, 128>>>(bufB, cw5, cb5, bufA);

    // head: pool + fc1 + fc2 + VQ + loss -> writes g_q and loss
    head_k<<<1, 256>>>(bufA, fc1_w, fc1_b, fc2_w, fc2_b, emb, loss_ptr);

    // big streaming GEMM: flat = q @ W_all
    { const int TPB = 256;
      long long nblk = (T2 + TPB - 1) / TPB;
      hyper_gemm_k<<<(unsigned)nblk, TPB>>>(W_all, out); }
}

// round 16
// speedup vs baseline: 1.1205x; 1.1205x over previous
#include <cuda_runtime.h>
#include <cuda_bf16.h>
#include <cstdint>

// ---------------- constants ----------------
#define BATCH 4
#define T_TOTAL 35968706LL          // sum of all hypernet parameter counts
#define T2 (T_TOTAL / 2)            // 17,984,353 float2 columns (T_TOTAL is even)

// ---------------- device scratch (no allocation allowed) ----------------
__device__ float g_bufA[4 * 4 * 112 * 112];   // 200,704 floats (largest intermediate)
__device__ float g_bufB[4 * 8 * 56 * 56];     // 100,352 floats
__device__ float g_q[BATCH * 16];             // quantized latents for the big GEMM
__device__ unsigned g_done = 0;               // last-block ticket for conv5+head fusion

// ---------------- templated 4x4 stride-2 pad-1 conv (full unroll) ----------------
// R7-proven configuration. SPLIT > 1: Cin reduction split across SPLIT adjacent
// lanes, reduced with __shfl_xor_sync.
template<int CIN, int COUT, int HIN, int HOUT, bool ACT, int SPLIT, int TPB>
__global__ void __launch_bounds__(TPB) convT(const float* __restrict__ in,
                                             const float* __restrict__ w,
                                             const float* __restrict__ bias,
                                             float* __restrict__ out) {
    constexpr int CPS = CIN / SPLIT;
    int tid = blockIdx.x * TPB + threadIdx.x;
    constexpr int TOTAL = BATCH * COUT * HOUT * HOUT * SPLIT;
    if (tid >= TOTAL) return;   // grids are exact multiples; never splits a warp

    int s = tid % SPLIT;
    int o = tid / SPLIT;
    int ow = o % HOUT;
    int oh = (o / HOUT) % HOUT;
    int co = (o / (HOUT * HOUT)) % COUT;
    int b  = o / (HOUT * HOUT * COUT);

    float acc = 0.0f;
    int ih0 = oh * 2 - 1;
    int iw0 = ow * 2 - 1;

    const float* wbase = w + ((size_t)co * CIN + s * CPS) * 16;
    const float* ibase = in + ((size_t)b * CIN + s * CPS) * HIN * HIN;

    #pragma unroll
    for (int ci = 0; ci < CPS; ci++) {
        const float* ip = ibase + (size_t)ci * HIN * HIN;
        const float* wp = wbase + ci * 16;
        #pragma unroll
        for (int kh = 0; kh < 4; kh++) {
            int ih = ih0 + kh;
            bool rowok = (unsigned)ih < (unsigned)HIN;
            #pragma unroll
            for (int kw = 0; kw < 4; kw++) {
                int iw = iw0 + kw;
                bool ok = rowok && ((unsigned)iw < (unsigned)HIN);
                float v = ok ? __ldg(ip + (size_t)ih * HIN + iw) : 0.0f;
                acc = fmaf(v, __ldg(wp + kh * 4 + kw), acc);
            }
        }
    }

    // in-warp reduction across the SPLIT slices (adjacent lanes)
    #pragma unroll
    for (int off = SPLIT / 2; off > 0; off >>= 1)
        acc += __shfl_xor_sync(0xffffffffu, acc, off);

    if (s == 0) {
        acc += bias[co];
        if (ACT) acc = (acc >= 0.0f) ? acc : 0.01f * acc;
        out[o] = acc;
    }
}

// ---------------- conv5 + fused head (last-block pattern) ----------------
// conv5: 32->64, 14->7, SPLIT=8, no activation, bias applied. TPB=128, grid=784.
// The LAST block to finish (atomic ticket after threadfence) runs the head:
// avgpool + fc1 + fc2 + VQ + loss, writing g_q and the loss scalar.
__global__ void __launch_bounds__(128) conv5_head_k(
    const float* __restrict__ in, const float* __restrict__ w,
    const float* __restrict__ bias, float* __restrict__ out,
    const float* __restrict__ fc1_w, const float* __restrict__ fc1_b,
    const float* __restrict__ fc2_w, const float* __restrict__ fc2_b,
    const float* __restrict__ emb,
    float* __restrict__ loss_out) {

    constexpr int CIN = 32, COUT = 64, HIN = 14, HOUT = 7, SPLIT = 8, TPB = 128;
    constexpr int CPS = CIN / SPLIT;
    int tid = blockIdx.x * TPB + threadIdx.x;

    {
        int s = tid % SPLIT;
        int o = tid / SPLIT;
        int ow = o % HOUT;
        int oh = (o / HOUT) % HOUT;
        int co = (o / (HOUT * HOUT)) % COUT;
        int b  = o / (HOUT * HOUT * COUT);

        float acc = 0.0f;
        int ih0 = oh * 2 - 1;
        int iw0 = ow * 2 - 1;

        const float* wbase = w + ((size_t)co * CIN + s * CPS) * 16;
        const float* ibase = in + ((size_t)b * CIN + s * CPS) * HIN * HIN;

        #pragma unroll
        for (int ci = 0; ci < CPS; ci++) {
            const float* ip = ibase + (size_t)ci * HIN * HIN;
            const float* wp = wbase + ci * 16;
            #pragma unroll
            for (int kh = 0; kh < 4; kh++) {
                int ih = ih0 + kh;
                bool rowok = (unsigned)ih < (unsigned)HIN;
                #pragma unroll
                for (int kw = 0; kw < 4; kw++) {
                    int iw = iw0 + kw;
                    bool ok = rowok && ((unsigned)iw < (unsigned)HIN);
                    float v = ok ? __ldg(ip + (size_t)ih * HIN + iw) : 0.0f;
                    acc = fmaf(v, __ldg(wp + kh * 4 + kw), acc);
                }
            }
        }

        #pragma unroll
        for (int off = SPLIT / 2; off > 0; off >>= 1)
            acc += __shfl_xor_sync(0xffffffffu, acc, off);

        if (s == 0) out[o] = acc + bias[co];   // no activation on conv5
    }

    // ---- last-block election ----
    __shared__ int is_last;
    __threadfence();                       // make this block's stores visible
    __syncthreads();
    if (threadIdx.x == 0) {
        unsigned t = atomicAdd(&g_done, 1u);
        is_last = (t == gridDim.x - 1u) ? 1 : 0;
        if (is_last) g_done = 0;           // reset for next graph replay
    }
    __syncthreads();
    if (!is_last) return;

    // ---- head (128 threads): pool + fc1 + fc2 + VQ + loss ----
    __shared__ float pooled[BATCH * 64];
    __shared__ float h[BATCH * 16];
    __shared__ float e[BATCH * 16];
    __shared__ float qv[BATCH * 16];
    int lt = threadIdx.x;
    const float* conv5 = out;

    for (int i = lt; i < BATCH * 64; i += 128) {
        const float* p = conv5 + (size_t)i * 49;
        float sum = 0.0f;
        #pragma unroll
        for (int j = 0; j < 49; j++) sum += p[j];
        pooled[i] = sum * (1.0f / 49.0f);
    }
    __syncthreads();

    if (lt < 64) {
        int b = lt / 16, i = lt % 16;
        float s = fc1_b[i];
        #pragma unroll
        for (int c = 0; c < 64; c++) s += pooled[b * 64 + c] * fc1_w[i * 64 + c];
        h[b * 16 + i] = (s >= 0.0f) ? s : 0.01f * s;
    }
    __syncthreads();

    if (lt < 64) {
        int b = lt / 16, j = lt % 16;
        float s = fc2_b[j];
        #pragma unroll
        for (int i = 0; i < 16; i++) s += h[b * 16 + i] * fc2_w[j * 16 + i];
        e[b * 16 + j] = s;
    }
    __syncthreads();

    if (lt < BATCH) {
        int b = lt;
        float best = 3.402823e38f;
        int bi = 0;
        for (int j = 0; j < 4; j++) {
            float d = 0.0f;
            #pragma unroll
            for (int k = 0; k < 16; k++) {
                float diff = e[b * 16 + k] - emb[j * 16 + k];
                d += diff * diff;
            }
            if (d < best) { best = d; bi = j; }
        }
        #pragma unroll
        for (int k = 0; k < 16; k++) qv[b * 16 + k] = emb[bi * 16 + k];
    }
    __syncthreads();

    if (lt == 0) {
        float s = 0.0f;
        #pragma unroll
        for (int n = 0; n < 64; n++) {
            float d = qv[n] - e[n];
            s += d * d;
        }
        *loss_out = 1.25f * (s * (1.0f / 64.0f));   // q_lat + 0.25 * e_lat
        #pragma unroll
        for (int n = 0; n < 64; n++) g_q[n] = qv[n];
    }
}

// ---------------- big GEMM: flat = q @ W_all, [4,16] x [16, T_TOTAL] ----------------
// FROZEN (R9-measured 396.9 us @ DRAM=90.7%, 7.19 TB/s): float2, 16 batched
// __ldcs loads (MLP=16 is load-bearing — halving it cost +56 us in R14), __stcs.
__global__ void __launch_bounds__(256) hyper_gemm_k(const float* __restrict__ W,
                                                    float* __restrict__ out) {
    __shared__ float qs[64];
    if (threadIdx.x < 64) qs[threadIdx.x] = g_q[threadIdx.x];
    __syncthreads();

    long long t2 = (long long)blockIdx.x * blockDim.x + threadIdx.x;
    if (t2 >= T2) return;

    float2 w[16];
    #pragma unroll
    for (int k = 0; k < 16; k++) {
        w[k] = __ldcs((const float2*)(W + (size_t)k * T_TOTAL) + t2);
    }

    #pragma unroll
    for (int b = 0; b < 4; b++) {
        float ax = 0.0f, ay = 0.0f;
        #pragma unroll
        for (int k = 0; k < 16; k++) {
            float qk = qs[b * 16 + k];
            ax = fmaf(qk, w[k].x, ax);
            ay = fmaf(qk, w[k].y, ay);
        }
        __stcs((float2*)(out + (size_t)b * T_TOTAL) + t2, make_float2(ax, ay));
    }
}

// ---------------- launch ----------------
extern "C" void kernel_launch(void* const* d_in, const int* in_sizes, int n_in,
                              void* d_out, int out_size) {
    const float* rgb   = (const float*)d_in[0];
    const float* cw1   = (const float*)d_in[1];
    const float* cb1   = (const float*)d_in[2];
    const float* cw2   = (const float*)d_in[3];
    const float* cb2   = (const float*)d_in[4];
    const float* cw3   = (const float*)d_in[5];
    const float* cb3   = (const float*)d_in[6];
    const float* cw4   = (const float*)d_in[7];
    const float* cb4   = (const float*)d_in[8];
    const float* cw5   = (const float*)d_in[9];
    const float* cb5   = (const float*)d_in[10];
    const float* fc1_w = (const float*)d_in[11];
    const float* fc1_b = (const float*)d_in[12];
    const float* fc2_w = (const float*)d_in[13];
    const float* fc2_b = (const float*)d_in[14];
    const float* emb   = (const float*)d_in[15];
    const float* W_all = (const float*)d_in[16];

    float* out = (float*)d_out;
    float* loss_ptr = out + (size_t)out_size - 1;   // flat first, loss scalar last

    float* bufA;  cudaGetSymbolAddress((void**)&bufA, g_bufA);
    float* bufB;  cudaGetSymbolAddress((void**)&bufB, g_bufB);

    // ---- exact R7 encoder configuration (best measured: 453.4 us total) ----
    // conv1: 3->4,  224->112, act — 200,704 threads
    convT<3, 4, 224, 112, true, 1, 256><<<784, 256>>>(rgb, cw1, cb1, bufA);
    // conv2: 4->8,  112->56, act — 100,352 threads
    convT<4, 8, 112, 56, true, 1, 256><<<392, 256>>>(bufA, cw2, cb2, bufB);
    // conv3: 8->16, 56->28, act, SPLIT=4 (shuffle) — 200,704 threads
    convT<8, 16, 56, 28, true, 4, 256><<<784, 256>>>(bufB, cw3, cb3, bufA);
    // conv4: 16->32, 28->14, act, SPLIT=4 (shuffle) — 100,352 threads
    convT<16, 32, 28, 14, true, 4, 128><<<784, 128>>>(bufA, cw4, cb4, bufB);
    // conv5 + fused head (last-block): 32->64, 14->7, SPLIT=8 — 100,352 threads
    conv5_head_k<<<784, 128>>>(bufB, cw5, cb5, bufA,
                               fc1_w, fc1_b, fc2_w, fc2_b, emb, loss_ptr);

    // big streaming GEMM: flat = q @ W_all
    { const int TPB = 256;
      long long nblk = (T2 + TPB - 1) / TPB;
      hyper_gemm_k<<<(unsigned)nblk, TPB>>>(W_all, out); }
}